// round 14
// baseline (speedup 1.0000x reference)
#include <cuda_runtime.h>
#include <cuda_fp16.h>
#include <stdint.h>

// Problem constants (from reference): N_NODES=100000, N_EDGES=3200000
#define NMAX 100000
#define EMAX 3200000

// Prep geometry: 384 threads load 384 float4 = 1536 floats = 256 nodes/block.
#define PREP_T 384
#define PREP_NODES 256

// Scratch: device globals (no allocation allowed in kernel_launch)
__device__ __half2 g_vh[NMAX];          // vm*e^{i*va} packed as half2 (4 B/node)
__device__ float4 g_acc4[NMAX / 2];     // (p_imb,q_imb) pairs, float4-aliased

// ---------------------------------------------------------------------------
// K1: per-node masked select + trig precompute + init accumulators.
// Phase 1: elementwise select, one float4 per thread (3 coalesced loads,
//          select in registers), staged to 4 KB smem.
// Phase 2: 256 threads/block each read 6 consecutive smem floats (one node),
//          sincos + half2/acc stores.
// Mask dtype probed per block (16 int32 words all in {0,1} <=> int32 mask).
// cols: VM=0 VA=1 PG=2 QG=3 PD=4 QD=5
// ---------------------------------------------------------------------------
__global__ void __launch_bounds__(PREP_T)
node_prep_kernel(const float4* __restrict__ pred4,
                 const float4* __restrict__ target4,
                 const void* __restrict__ mask_raw,
                 float* __restrict__ out,
                 int n)
{
    __shared__ float ssel[PREP_T * 4];   // 1536 floats = 256 nodes

    // mask dtype probe (uniform across grid)
    bool okp = true;
    if (threadIdx.x < 16) {
        uint32_t v = ((const uint32_t*)mask_raw)[threadIdx.x];
        okp = (v <= 1u);
    }
    int mask_is32 = __syncthreads_and(okp);

    int totalFloats = n * 6;
    int totalF4     = totalFloats >> 2;          // full float4s
    int f = blockIdx.x * PREP_T + threadIdx.x;   // global float4 index

    if (blockIdx.x == 0 && threadIdx.x == 0) out[0] = 0.0f;

    // ---- Phase 1: elementwise select, stage to smem -----------------------
    if (f < totalF4) {
        float4 p = __ldcs(&pred4[f]);
        float4 t = __ldcs(&target4[f]);
        float4 sel;
        if (mask_is32) {
            uint4 mw = __ldcs(&((const uint4*)mask_raw)[f]);
            sel.x = mw.x ? p.x : t.x;
            sel.y = mw.y ? p.y : t.y;
            sel.z = mw.z ? p.z : t.z;
            sel.w = mw.w ? p.w : t.w;
        } else {
            uint32_t mb = __ldcs(&((const uint32_t*)mask_raw)[f]);
            sel.x = (mb & 0x000000FFu) ? p.x : t.x;
            sel.y = (mb & 0x0000FF00u) ? p.y : t.y;
            sel.z = (mb & 0x00FF0000u) ? p.z : t.z;
            sel.w = (mb & 0xFF000000u) ? p.w : t.w;
        }
        ((float4*)ssel)[threadIdx.x] = sel;
    }
    // scalar tail floats (totalFloats % 4) — only in the very last block
    if (f == totalF4 && (totalFloats & 3)) {
        const float* pf = (const float*)pred4;
        const float* tf = (const float*)target4;
        for (int k = 0; k < (totalFloats & 3); k++) {
            int idx = totalF4 * 4 + k;
            int mk;
            if (mask_is32) mk = ((const int*)mask_raw)[idx];
            else           mk = ((const unsigned char*)mask_raw)[idx];
            ssel[threadIdx.x * 4 + k] = mk ? pf[idx] : tf[idx];
        }
    }
    __syncthreads();

    // ---- Phase 2: per-node compute ----------------------------------------
    int li = threadIdx.x;
    if (li < PREP_NODES) {
        int i = blockIdx.x * PREP_NODES + li;
        if (i < n) {
            float v0 = ssel[li * 6 + 0];
            float v1 = ssel[li * 6 + 1];
            float v2 = ssel[li * 6 + 2];
            float v3 = ssel[li * 6 + 3];
            float v4 = ssel[li * 6 + 4];
            float v5 = ssel[li * 6 + 5];

            float s, c;
            sincosf(v1, &s, &c);
            g_vh[i] = __floats2half2_rn(v0 * c, v0 * s);
            ((float2*)g_acc4)[i] = make_float2(v2 - v4, v3 - v5);
        }
    }
}

// ---------------------------------------------------------------------------
// K2: 4 edges per thread (proven best). Stream loads via .cs (evict-first),
// all 8 half2 node gathers issued up-front for MLP, fp32 flow math,
// one red.global.add.v2.f32 per edge.
//   vv*cos(dva) = xs*xd + ys*yd ;  vv*sin(dva) = ys*xd - xs*yd
// Edge-index dtype probed per block (JAX demotes int64->int32 unless x64).
// ---------------------------------------------------------------------------
__global__ void edge_kernel(const void* __restrict__ ei_raw,
                            const float* __restrict__ ea,
                            int E, int n)
{
    bool ok = true;
    if (threadIdx.x < 16) {
        long long v = ((const long long*)ei_raw)[threadIdx.x];
        ok = (v >= 0 && v < (long long)n);
    }
    int is64 = __syncthreads_and(ok);

    int e = (blockIdx.x * blockDim.x + threadIdx.x) * 4;
    if (e >= E) return;

    float2* acc = (float2*)g_acc4;

    if (e + 3 < E) {
        int s[4], d[4];
        if (is64) {
            const long long* ei = (const long long*)ei_raw;
            longlong2 s01 = __ldcs((const longlong2*)(ei + e));
            longlong2 s23 = __ldcs((const longlong2*)(ei + e + 2));
            longlong2 d01 = __ldcs((const longlong2*)(ei + E + e));
            longlong2 d23 = __ldcs((const longlong2*)(ei + E + e + 2));
            s[0] = (int)s01.x; s[1] = (int)s01.y; s[2] = (int)s23.x; s[3] = (int)s23.y;
            d[0] = (int)d01.x; d[1] = (int)d01.y; d[2] = (int)d23.x; d[3] = (int)d23.y;
        } else {
            const int* ei = (const int*)ei_raw;
            int4 sv = __ldcs((const int4*)(ei + e));
            int4 dv = __ldcs((const int4*)(ei + E + e));
            s[0] = sv.x; s[1] = sv.y; s[2] = sv.z; s[3] = sv.w;
            d[0] = dv.x; d[1] = dv.y; d[2] = dv.z; d[3] = dv.w;
        }
        float4 gb01 = __ldcs((const float4*)(ea + (size_t)e * 2));
        float4 gb23 = __ldcs((const float4*)(ea + (size_t)e * 2 + 4));

        // issue all gathers first (independent -> high MLP)
        __half2 ush[4], udh[4];
#pragma unroll
        for (int k = 0; k < 4; k++) ush[k] = __ldg(&g_vh[s[k]]);
#pragma unroll
        for (int k = 0; k < 4; k++) udh[k] = __ldg(&g_vh[d[k]]);

        float gg[4] = {gb01.x, gb01.z, gb23.x, gb23.z};
        float bb[4] = {gb01.y, gb01.w, gb23.y, gb23.w};

#pragma unroll
        for (int k = 0; k < 4; k++) {
            float2 us = __half22float2(ush[k]);
            float2 ud = __half22float2(udh[k]);
            float vvc = us.x * ud.x + us.y * ud.y;
            float vvs = us.y * ud.x - us.x * ud.y;
            float pf = gg[k] * vvc + bb[k] * vvs;
            float qf = gg[k] * vvs - bb[k] * vvc;
            asm volatile("red.global.add.v2.f32 [%0], {%1, %2};"
                         :: "l"(&acc[s[k]]), "f"(-pf), "f"(-qf)
                         : "memory");
        }
    } else {
        for (int k = e; k < E; k++) {
            int s0, d0;
            if (is64) {
                const long long* ei = (const long long*)ei_raw;
                s0 = (int)ei[k];
                d0 = (int)ei[E + k];
            } else {
                const int* ei = (const int*)ei_raw;
                s0 = ei[k];
                d0 = ei[E + k];
            }
            float gg = ea[(size_t)k * 2];
            float bb = ea[(size_t)k * 2 + 1];
            float2 us = __half22float2(__ldg(&g_vh[s0]));
            float2 ud = __half22float2(__ldg(&g_vh[d0]));
            float vvc = us.x * ud.x + us.y * ud.y;
            float vvs = us.y * ud.x - us.x * ud.y;
            float pf = gg * vvc + bb * vvs;
            float qf = gg * vvs - bb * vvc;
            asm volatile("red.global.add.v2.f32 [%0], {%1, %2};"
                         :: "l"(&acc[s0]), "f"(-pf), "f"(-qf)
                         : "memory");
        }
    }
}

// ---------------------------------------------------------------------------
// K3: sum of squares, scaled by 1/n, atomically added into out[0]
// (zeroed by node_prep earlier in the stream). One float4 per thread.
// ---------------------------------------------------------------------------
__global__ void reduce_kernel(float* __restrict__ out, int n)
{
    int nq = n / 2;   // float4 count (pairs; odd tail handled below)
    int i = blockIdx.x * blockDim.x + threadIdx.x;

    float sum = 0.0f;
    if (i < nq) {
        float4 a = g_acc4[i];
        sum = a.x * a.x + a.y * a.y + a.z * a.z + a.w * a.w;
    }
    if (i == 0 && (n & 1)) {
        float2 a = ((const float2*)g_acc4)[n - 1];
        sum += a.x * a.x + a.y * a.y;
    }

#pragma unroll
    for (int off = 16; off > 0; off >>= 1)
        sum += __shfl_down_sync(0xFFFFFFFFu, sum, off);

    __shared__ float warp_sums[32];
    int lane = threadIdx.x & 31;
    int wid  = threadIdx.x >> 5;
    if (lane == 0) warp_sums[wid] = sum;
    __syncthreads();

    int nwarps = (blockDim.x + 31) >> 5;
    if (wid == 0) {
        float bsum = (lane < nwarps) ? warp_sums[lane] : 0.0f;
#pragma unroll
        for (int off = 16; off > 0; off >>= 1)
            bsum += __shfl_down_sync(0xFFFFFFFFu, bsum, off);
        if (lane == 0)
            atomicAdd(out, bsum / (float)n);
    }
}

extern "C" void kernel_launch(void* const* d_in, const int* in_sizes, int n_in,
                              void* d_out, int out_size)
{
    const float* pred       = (const float*)d_in[0];
    const float* target     = (const float*)d_in[1];
    const void*  edge_index = d_in[2];
    const float* edge_attr  = (const float*)d_in[3];
    const void*  mask       = d_in[4];

    int n = in_sizes[0] / 6;       // nodes
    int E = in_sizes[2] / 2;       // edges
    if (n > NMAX) n = NMAX;
    if (E > EMAX) E = EMAX;

    float* out = (float*)d_out;

    const int B = 256;
    int pgrid = (n + PREP_NODES - 1) / PREP_NODES;
    node_prep_kernel<<<pgrid, PREP_T>>>((const float4*)pred,
                                        (const float4*)target,
                                        mask, out, n);
    int equads = (E + 3) / 4;
    edge_kernel<<<(equads + B - 1) / B, B>>>(edge_index, edge_attr, E, n);
    int nq = n / 2;
    reduce_kernel<<<(nq + B - 1) / B, B>>>(out, n);
}